// round 14
// baseline (speedup 1.0000x reference)
#include <cuda_runtime.h>

#define EPS 1e-5f

// ---------------- scratch (device globals; no allocations allowed) ----------
static __device__ float g_act1[256*64*32*32];   // 64 MB
static __device__ float g_act2[256*128*16*16];  // 32 MB
static __device__ float g_act3[256*256*8*8];    // 16 MB
static __device__ float g_M[256*64*50];         // 3.3 MB
static __device__ float g_ob[256*64];

__device__ __forceinline__ float lrelu(float v) { return v >= 0.f ? v : 0.2f*v; }

typedef unsigned long long ull;
__device__ __forceinline__ void upk2(ull v, float& a, float& b) {
    unsigned int lo, hi;
    asm("mov.b64 {%0, %1}, %2;" : "=r"(lo), "=r"(hi) : "l"(v));
    a = __uint_as_float(lo); b = __uint_as_float(hi);
}
__device__ __forceinline__ ull fma2(ull a, ull b, ull c) {
    ull d;
    asm("fma.rn.f32x2 %0, %1, %2, %3;" : "=l"(d) : "l"(a), "l"(b), "l"(c));
    return d;
}

// ============================================================================
// conv1: x(256,3,64,64) * w1(64,3,5,5) s2 p2 -> (256,64,32,32), IN + lrelu
// (unchanged — known good)
// ============================================================================
__global__ void __launch_bounds__(256) conv1_kernel(
    const float* __restrict__ x, const float* __restrict__ w,
    const float* __restrict__ b, const float* __restrict__ g,
    const float* __restrict__ be)
{
    const int c_out = blockIdx.x;
    const int n = blockIdx.y;
    const int tid = threadIdx.x;
    const int by = tid >> 4, bx = tid & 15;

    __shared__ float s_in[68*68];
    __shared__ float s_w[75];
    __shared__ float s_r[256];
    __shared__ float s_q[256];

    if (tid < 75) s_w[tid] = w[c_out*75 + tid];

    float acc[4] = {0.f, 0.f, 0.f, 0.f};

    for (int c = 0; c < 3; ++c) {
        __syncthreads();
        const float* xp = x + ((n*3 + c) << 12);
        for (int idx = tid; idx < 68*68; idx += 256) {
            int sy = idx / 68;
            int sx = idx - sy*68;
            sy -= 2; sx -= 2;
            float v = 0.f;
            if (sy >= 0 && sy < 64 && sx >= 0 && sx < 64) v = xp[(sy << 6) + sx];
            s_in[idx] = v;
        }
        __syncthreads();
        const float* tin = s_in + (by*4)*68 + bx*4;
        const float* tw  = s_w + c*25;
        #pragma unroll
        for (int ky = 0; ky < 5; ++ky) {
            #pragma unroll
            for (int kx = 0; kx < 5; ++kx) {
                float wv = tw[ky*5 + kx];
                acc[0] += tin[ky*68 + kx]       * wv;
                acc[1] += tin[ky*68 + kx + 2]   * wv;
                acc[2] += tin[(ky+2)*68 + kx]   * wv;
                acc[3] += tin[(ky+2)*68 + kx+2] * wv;
            }
        }
    }

    float bc = b[c_out];
    float lv = 0.f, lq = 0.f;
    #pragma unroll
    for (int p = 0; p < 4; ++p) { acc[p] += bc; lv += acc[p]; lq += acc[p]*acc[p]; }

    __syncthreads();
    s_r[tid] = lv; s_q[tid] = lq;
    __syncthreads();
    for (int s = 128; s > 0; s >>= 1) {
        if (tid < s) { s_r[tid] += s_r[tid+s]; s_q[tid] += s_q[tid+s]; }
        __syncthreads();
    }
    float mean = s_r[0] * (1.f/1024.f);
    float var  = fmaxf(s_q[0] * (1.f/1024.f) - mean*mean, 0.f);
    float scale = g[c_out] * rsqrtf(var + EPS);
    float shift = be[c_out] - mean*scale;

    float* outp = g_act1 + ((n*64 + c_out) << 10);
    outp[(by*2+0)*32 + bx*2+0] = lrelu(acc[0]*scale + shift);
    outp[(by*2+0)*32 + bx*2+1] = lrelu(acc[1]*scale + shift);
    outp[(by*2+1)*32 + bx*2+0] = lrelu(acc[2]*scale + shift);
    outp[(by*2+1)*32 + bx*2+1] = lrelu(acc[3]*scale + shift);
}

// ============================================================================
// conv2: act1(256,64,32,32) * w2(128,64,5,5) s2 p2 -> (256,128,16,16), IN+lrelu
// f32x2 channel-pairs. 256 thr; warp = 2 couts; lane = (oy, seg half-row).
// s_in interleaves channel pairs -> LDS.64 operands, zero ALU packing.
// ============================================================================
__global__ void __launch_bounds__(256) conv2_kernel(
    const float* __restrict__ w, const float* __restrict__ b,
    const float* __restrict__ g, const float* __restrict__ be)
{
    const int c0 = blockIdx.x * 16;           // gridDim.x = 8
    const int n  = blockIdx.y;
    const int tid  = threadIdx.x;             // 256
    const int wid  = tid >> 5;                // 0..7 -> couts c0+wid*2+u
    const int lane = tid & 31;
    const int oy   = lane >> 1;               // 0..15
    const int seg  = lane & 1;                // ox base 8*seg

    __shared__ __align__(16) float s_in[2*36*37*2];   // [pr][iy][ix][c] 21.3KB
    __shared__ __align__(16) float s_w[1600];         // [pr][clo16][t25][c] 6.4KB

    ull acc2[2][8];
    #pragma unroll
    for (int u = 0; u < 2; ++u)
        #pragma unroll
        for (int p = 0; p < 8; ++p) acc2[u][p] = 0ull;

    const float* inbase = g_act1 + ((n*64) << 10);

    for (int cc = 0; cc < 64; cc += 4) {
        __syncthreads();
        for (int idx = tid; idx < 1600; idx += 256) {
            int c = idx & 1;
            int q = idx >> 1;
            int t = q % 25;
            int r = q / 25;
            int clo = r & 15, pr = r >> 4;
            s_w[idx] = w[(c0 + clo)*1600 + (cc + pr*2 + c)*25 + t];
        }
        for (int idx = tid; idx < 5184; idx += 256) {
            int ch = idx / 1296;
            int r  = idx - ch*1296;
            int iy = r / 36;
            int ix = r - iy*36;
            float v = 0.f;
            int gy = iy - 2, gx = ix - 2;
            if (gy >= 0 && gy < 32 && gx >= 0 && gx < 32)
                v = inbase[((cc + ch) << 10) + (gy << 5) + gx];
            s_in[(ch >> 1)*2664 + (iy*37 + ix)*2 + (ch & 1)] = v;
        }
        __syncthreads();
        #pragma unroll
        for (int pr = 0; pr < 2; ++pr) {
            const float* swp = s_w + pr*800 + (wid*2)*50;
            const float* sip = s_in + pr*2664 + seg*32;
            #pragma unroll
            for (int ky = 0; ky < 5; ++ky) {
                const float* row = sip + (2*oy + ky)*74;
                ull r2[19];
                #pragma unroll
                for (int j = 0; j < 19; ++j) r2[j] = *(const ull*)(row + j*2);
                #pragma unroll
                for (int kx = 0; kx < 5; ++kx) {
                    ull w20 = *(const ull*)(swp + (ky*5 + kx)*2);
                    ull w21 = *(const ull*)(swp + 50 + (ky*5 + kx)*2);
                    #pragma unroll
                    for (int p = 0; p < 8; ++p) {
                        acc2[0][p] = fma2(r2[2*p + kx], w20, acc2[0][p]);
                        acc2[1][p] = fma2(r2[2*p + kx], w21, acc2[1][p]);
                    }
                }
            }
        }
    }

    // epilogue: warp owns each cout's full 256-px plane
    #pragma unroll
    for (int u = 0; u < 2; ++u) {
        int co = c0 + wid*2 + u;
        float bc = b[co];
        float val[8];
        float lv = 0.f, lq = 0.f;
        #pragma unroll
        for (int p = 0; p < 8; ++p) {
            float lo, hi; upk2(acc2[u][p], lo, hi);
            val[p] = lo + hi + bc;
            lv += val[p]; lq += val[p]*val[p];
        }
        #pragma unroll
        for (int off = 16; off >= 1; off >>= 1) {
            lv += __shfl_xor_sync(0xffffffffu, lv, off);
            lq += __shfl_xor_sync(0xffffffffu, lq, off);
        }
        float mean = lv * (1.f/256.f);
        float var  = fmaxf(lq * (1.f/256.f) - mean*mean, 0.f);
        float scale = g[co] * rsqrtf(var + EPS);
        float shift = be[co] - mean*scale;
        float* p0 = g_act2 + ((n*128 + co) << 8) + oy*16 + seg*8;
        float4 o0, o1;
        o0.x = lrelu(val[0]*scale + shift); o0.y = lrelu(val[1]*scale + shift);
        o0.z = lrelu(val[2]*scale + shift); o0.w = lrelu(val[3]*scale + shift);
        o1.x = lrelu(val[4]*scale + shift); o1.y = lrelu(val[5]*scale + shift);
        o1.z = lrelu(val[6]*scale + shift); o1.w = lrelu(val[7]*scale + shift);
        *(float4*)(p0)     = o0;
        *(float4*)(p0 + 4) = o1;
    }
}

// ============================================================================
// conv3: act2(256,128,16,16) * w3(256,128,5,5) s2 p2 -> (256,256,8,8), IN+lrelu
// f32x2 channel-pairs. 256 thr; thread = 2 couts x full 8-px row.
// ============================================================================
__global__ void __launch_bounds__(256) conv3_kernel(
    const float* __restrict__ w, const float* __restrict__ b,
    const float* __restrict__ g, const float* __restrict__ be)
{
    const int c0 = blockIdx.x * 64;           // gridDim.x = 4
    const int n  = blockIdx.y;
    const int tid = threadIdx.x;              // 256
    const int grp = tid >> 3;                 // 0..31 -> couts c0+grp*2+u
    const int oy  = tid & 7;                  // output row

    __shared__ __align__(16) float s_in[2*20*21*2];   // [pr][iy][ix][c] 6.7KB
    __shared__ __align__(16) float s_w[6400];         // [pr][clo64][t25][c] 25.6KB

    ull acc2[2][8];
    #pragma unroll
    for (int u = 0; u < 2; ++u)
        #pragma unroll
        for (int p = 0; p < 8; ++p) acc2[u][p] = 0ull;

    const float* inbase = g_act2 + ((n*128) << 8);

    for (int cc = 0; cc < 128; cc += 4) {
        __syncthreads();
        for (int idx = tid; idx < 6400; idx += 256) {
            int c = idx & 1;
            int q = idx >> 1;
            int t = q % 25;
            int r = q / 25;
            int clo = r & 63, pr = r >> 6;
            s_w[idx] = w[(c0 + clo)*3200 + (cc + pr*2 + c)*25 + t];
        }
        for (int idx = tid; idx < 1600; idx += 256) {
            int ch = idx / 400;
            int r  = idx - ch*400;
            int iy = r / 20;
            int ix = r - iy*20;
            float v = 0.f;
            int gy = iy - 2, gx = ix - 2;
            if (gy >= 0 && gy < 16 && gx >= 0 && gx < 16)
                v = inbase[((cc + ch) << 8) + (gy << 4) + gx];
            s_in[(ch >> 1)*840 + (iy*21 + ix)*2 + (ch & 1)] = v;
        }
        __syncthreads();
        #pragma unroll
        for (int pr = 0; pr < 2; ++pr) {
            const float* swp = s_w + pr*3200 + (grp*2)*50;
            const float* sip = s_in + pr*840;
            #pragma unroll
            for (int ky = 0; ky < 5; ++ky) {
                const float* row = sip + (2*oy + ky)*42;
                ull r2[19];
                #pragma unroll
                for (int j = 0; j < 19; ++j) r2[j] = *(const ull*)(row + j*2);
                #pragma unroll
                for (int kx = 0; kx < 5; ++kx) {
                    ull w20 = *(const ull*)(swp + (ky*5 + kx)*2);
                    ull w21 = *(const ull*)(swp + 50 + (ky*5 + kx)*2);
                    #pragma unroll
                    for (int p = 0; p < 8; ++p) {
                        acc2[0][p] = fma2(r2[2*p + kx], w20, acc2[0][p]);
                        acc2[1][p] = fma2(r2[2*p + kx], w21, acc2[1][p]);
                    }
                }
            }
        }
    }

    // epilogue: 8 consecutive lanes own each cout's 64-px plane
    #pragma unroll
    for (int u = 0; u < 2; ++u) {
        int co = c0 + grp*2 + u;
        float bc = b[co];
        float val[8];
        float lv = 0.f, lq = 0.f;
        #pragma unroll
        for (int p = 0; p < 8; ++p) {
            float lo, hi; upk2(acc2[u][p], lo, hi);
            val[p] = lo + hi + bc;
            lv += val[p]; lq += val[p]*val[p];
        }
        #pragma unroll
        for (int off = 4; off >= 1; off >>= 1) {
            lv += __shfl_xor_sync(0xffffffffu, lv, off);
            lq += __shfl_xor_sync(0xffffffffu, lq, off);
        }
        float mean = lv * (1.f/64.f);
        float var  = fmaxf(lq * (1.f/64.f) - mean*mean, 0.f);
        float scale = g[co] * rsqrtf(var + EPS);
        float shift = be[co] - mean*scale;
        float* p0 = g_act3 + ((n*256 + co) << 6) + oy*8;
        float4 o0, o1;
        o0.x = lrelu(val[0]*scale + shift); o0.y = lrelu(val[1]*scale + shift);
        o0.z = lrelu(val[2]*scale + shift); o0.w = lrelu(val[3]*scale + shift);
        o1.x = lrelu(val[4]*scale + shift); o1.y = lrelu(val[5]*scale + shift);
        o1.z = lrelu(val[6]*scale + shift); o1.w = lrelu(val[7]*scale + shift);
        *(float4*)(p0)     = o0;
        *(float4*)(p0 + 4) = o1;
    }
}

// ============================================================================
// conv4: (unchanged from R13 — known good)
// ============================================================================
__global__ void __launch_bounds__(256) conv4_kernel(
    const float* __restrict__ w, const float* __restrict__ b,
    const float* __restrict__ g, const float* __restrict__ be,
    float* __restrict__ feat)
{
    const int c0   = blockIdx.x * 128;        // gridDim.x = 2
    const int n    = blockIdx.y;
    const int tid  = threadIdx.x;             // 256
    const int half = tid >> 7;                // ch half
    const int sid  = tid & 127;
    const int grp  = sid >> 2;                // 0..31 -> couts c0+grp*4+u
    const int oy   = sid & 3;                 // output row

    __shared__ float s_in[2][4*110];
    __shared__ float s_w[2][128*37];
    __shared__ float s_m[128*17];

    float acc[4][4];
    #pragma unroll
    for (int u = 0; u < 4; ++u)
        #pragma unroll
        for (int p = 0; p < 4; ++p) acc[u][p] = 0.f;

    const float* inbase = g_act3 + ((n*256) << 6) + (half << 13);
    const int wchbase = half*128;

    for (int cc = 0; cc < 128; cc += 4) {
        __syncthreads();
        for (int idx = sid; idx < 440; idx += 128) {
            int ch = idx / 110;
            int r  = idx - ch*110;
            int iy = r / 11;
            int ix = r - iy*11;
            float v = 0.f;
            int gy = iy - 1, gx = ix - 1;
            if (gy >= 0 && gy < 8 && gx >= 0 && gx < 8)
                v = inbase[((cc + ch) << 6) + (gy << 3) + gx];
            s_in[half][ch*110 + iy*11 + ix] = v;
        }
        for (int idx = sid; idx < 4608; idx += 128) {
            int clo = idx / 36;
            int r   = idx - clo*36;
            s_w[half][clo*37 + r] = w[(c0 + clo)*2304 + (wchbase + cc)*9 + r];
        }
        __syncthreads();
        #pragma unroll
        for (int ch = 0; ch < 4; ++ch) {
            const float* si = s_in[half] + ch*110;
            float rr[3][9];
            #pragma unroll
            for (int ky = 0; ky < 3; ++ky) {
                const float* row = si + (2*oy + ky)*11;
                #pragma unroll
                for (int j = 0; j < 9; ++j) rr[ky][j] = row[j];
            }
            const float* sw = s_w[half] + (grp*4)*37 + ch*9;
            #pragma unroll
            for (int ky = 0; ky < 3; ++ky) {
                #pragma unroll
                for (int kx = 0; kx < 3; ++kx) {
                    float wv[4];
                    #pragma unroll
                    for (int u = 0; u < 4; ++u) wv[u] = sw[u*37 + ky*3 + kx];
                    #pragma unroll
                    for (int u = 0; u < 4; ++u)
                        #pragma unroll
                        for (int p = 0; p < 4; ++p)
                            acc[u][p] += rr[ky][2*p + kx] * wv[u];
                }
            }
        }
    }

    __syncthreads();
    if (half == 1) {
        #pragma unroll
        for (int u = 0; u < 4; ++u)
            #pragma unroll
            for (int p = 0; p < 4; ++p)
                s_m[sid*17 + u*4 + p] = acc[u][p];
    }
    __syncthreads();
    if (half == 0) {
        #pragma unroll
        for (int u = 0; u < 4; ++u)
            #pragma unroll
            for (int p = 0; p < 4; ++p)
                acc[u][p] += s_m[sid*17 + u*4 + p];

        #pragma unroll
        for (int u = 0; u < 4; ++u) {
            int co = c0 + grp*4 + u;
            float bc = b[co];
            float lv = 0.f, lq = 0.f;
            #pragma unroll
            for (int p = 0; p < 4; ++p) {
                acc[u][p] += bc; lv += acc[u][p]; lq += acc[u][p]*acc[u][p];
            }
            #pragma unroll
            for (int off = 2; off >= 1; off >>= 1) {
                lv += __shfl_xor_sync(0xffffffffu, lv, off);
                lq += __shfl_xor_sync(0xffffffffu, lq, off);
            }
            float mean = lv * (1.f/16.f);
            float var  = fmaxf(lq * (1.f/16.f) - mean*mean, 0.f);
            float scale = g[co] * rsqrtf(var + EPS);
            float shift = be[co] - mean*scale;
            float4 o;
            o.x = lrelu(acc[u][0]*scale + shift); o.y = lrelu(acc[u][1]*scale + shift);
            o.z = lrelu(acc[u][2]*scale + shift); o.w = lrelu(acc[u][3]*scale + shift);
            *(float4*)(feat + n*4096 + (co << 4) + oy*4) = o;
        }
    }
}

// ============================================================================
// M = feat(256x4096) @ T(4096x3200), register-prefetch (unchanged)
// ============================================================================
__global__ void __launch_bounds__(256) gemmM_kernel(
    const float* __restrict__ A, const float* __restrict__ B)
{
    const int n0 = blockIdx.x * 64;
    const int m0 = blockIdx.y * 64;
    const int tid = threadIdx.x;
    const int tx = tid & 15, ty = tid >> 4;

    __shared__ float sA[16*65];
    __shared__ float sB[16*64];

    float acc[4][4];
    #pragma unroll
    for (int i = 0; i < 4; ++i)
        #pragma unroll
        for (int j = 0; j < 4; ++j) acc[i][j] = 0.f;

    const int lrow = tid >> 2;
    const int lkk  = (tid & 3) << 2;
    const int bk   = tid >> 4;
    const int bj   = (tid & 15) << 2;

    float4 va = *(const float4*)(A + (m0 + lrow)*4096 + lkk);
    float4 vb = *(const float4*)(B + bk*3200 + n0 + bj);

    for (int kt = 0; kt < 4096; kt += 16) {
        sA[(lkk+0)*65 + lrow] = va.x;
        sA[(lkk+1)*65 + lrow] = va.y;
        sA[(lkk+2)*65 + lrow] = va.z;
        sA[(lkk+3)*65 + lrow] = va.w;
        *(float4*)(sB + bk*64 + bj) = vb;
        __syncthreads();
        if (kt + 16 < 4096) {
            va = *(const float4*)(A + (m0 + lrow)*4096 + kt + 16 + lkk);
            vb = *(const float4*)(B + (kt + 16 + bk)*3200 + n0 + bj);
        }
        #pragma unroll
        for (int k = 0; k < 16; ++k) {
            float a[4], bb[4];
            #pragma unroll
            for (int i = 0; i < 4; ++i) a[i]  = sA[k*65 + ty*4 + i];
            #pragma unroll
            for (int j = 0; j < 4; ++j) bb[j] = sB[k*64 + tx*4 + j];
            #pragma unroll
            for (int i = 0; i < 4; ++i)
                #pragma unroll
                for (int j = 0; j < 4; ++j) acc[i][j] += a[i]*bb[j];
        }
        __syncthreads();
    }
    #pragma unroll
    for (int i = 0; i < 4; ++i)
        #pragma unroll
        for (int j = 0; j < 4; ++j)
            g_M[(m0 + ty*4 + i)*3200 + n0 + tx*4 + j] = acc[i][j];
}

// ============================================================================
// o_b (unchanged)
// ============================================================================
__global__ void __launch_bounds__(256) ob_kernel()
{
    const int o = blockIdx.x;
    const int j = blockIdx.y;
    const int tid = threadIdx.x;

    __shared__ float2 s_mj[25];
    __shared__ float s_red[256];

    if (tid < 25) s_mj[tid] = *(const float2*)(g_M + j*3200 + o*50 + tid*2);
    __syncthreads();

    const float2* mi = (const float2*)(g_M + tid*3200 + o*50);
    float d = 0.f;
    #pragma unroll
    for (int k = 0; k < 25; ++k) {
        float2 a = mi[k], bb = s_mj[k];
        d += fabsf(a.x - bb.x) + fabsf(a.y - bb.y);
    }
    s_red[tid] = expf(-d);
    __syncthreads();
    for (int s = 128; s > 0; s >>= 1) {
        if (tid < s) s_red[tid] += s_red[tid+s];
        __syncthreads();
    }
    if (tid == 0) g_ob[j*64 + o] = s_red[0] - 1.0f;
}

// ============================================================================
// y = [feat | o_b] @ fc_w^T + fc_b (unchanged)
// ============================================================================
__global__ void __launch_bounds__(256) fc_kernel(
    const float* __restrict__ feat, const float* __restrict__ Wt,
    const float* __restrict__ bias, float* __restrict__ y)
{
    const int n0 = blockIdx.x * 64;
    const int m0 = blockIdx.y * 64;
    const int tid = threadIdx.x;
    const int tx = tid & 15, ty = tid >> 4;

    __shared__ float sA[16*65];
    __shared__ float sB[16*65];

    float acc[4][4];
    #pragma unroll
    for (int i = 0; i < 4; ++i)
        #pragma unroll
        for (int j = 0; j < 4; ++j) acc[i][j] = 0.f;

    const int lrow = tid >> 2;
    const int lkk  = (tid & 3) << 2;
    const bool bvalid = (n0 + lrow) < 1000;

    float4 va = *(const float4*)(feat + (m0 + lrow)*4096 + lkk);
    float4 vb = bvalid ? *(const float4*)(Wt + (n0 + lrow)*4160 + lkk)
                       : make_float4(0.f, 0.f, 0.f, 0.f);

    for (int kt = 0; kt < 4160; kt += 16) {
        sA[(lkk+0)*65 + lrow] = va.x;
        sA[(lkk+1)*65 + lrow] = va.y;
        sA[(lkk+2)*65 + lrow] = va.z;
        sA[(lkk+3)*65 + lrow] = va.w;
        sB[(lkk+0)*65 + lrow] = vb.x;
        sB[(lkk+1)*65 + lrow] = vb.y;
        sB[(lkk+2)*65 + lrow] = vb.z;
        sB[(lkk+3)*65 + lrow] = vb.w;
        __syncthreads();
        int knext = kt + 16;
        if (knext < 4160) {
            va = (knext < 4096)
               ? *(const float4*)(feat + (m0 + lrow)*4096 + knext + lkk)
               : *(const float4*)(g_ob + (m0 + lrow)*64 + (knext - 4096) + lkk);
            vb = bvalid ? *(const float4*)(Wt + (n0 + lrow)*4160 + knext + lkk)
                        : make_float4(0.f, 0.f, 0.f, 0.f);
        }
        #pragma unroll
        for (int k = 0; k < 16; ++k) {
            float a[4], bb[4];
            #pragma unroll
            for (int i = 0; i < 4; ++i) a[i]  = sA[k*65 + ty*4 + i];
            #pragma unroll
            for (int j = 0; j < 4; ++j) bb[j] = sB[k*65 + tx*4 + j];
            #pragma unroll
            for (int i = 0; i < 4; ++i)
                #pragma unroll
                for (int j = 0; j < 4; ++j) acc[i][j] += a[i]*bb[j];
        }
        __syncthreads();
    }
    #pragma unroll
    for (int i = 0; i < 4; ++i) {
        #pragma unroll
        for (int j = 0; j < 4; ++j) {
            int nn = n0 + tx*4 + j;
            if (nn < 1000)
                y[(m0 + ty*4 + i)*1000 + nn] = acc[i][j] + bias[nn];
        }
    }
}

// ============================================================================
extern "C" void kernel_launch(void* const* d_in, const int* in_sizes, int n_in,
                              void* d_out, int out_size)
{
    (void)in_sizes; (void)n_in; (void)out_size;
    const float* x    = (const float*)d_in[0];
    const float* w1   = (const float*)d_in[1];
    const float* b1   = (const float*)d_in[2];
    const float* g1   = (const float*)d_in[3];
    const float* be1  = (const float*)d_in[4];
    const float* w2   = (const float*)d_in[5];
    const float* b2   = (const float*)d_in[6];
    const float* g2   = (const float*)d_in[7];
    const float* be2  = (const float*)d_in[8];
    const float* w3   = (const float*)d_in[9];
    const float* b3   = (const float*)d_in[10];
    const float* g3   = (const float*)d_in[11];
    const float* be3  = (const float*)d_in[12];
    const float* w4   = (const float*)d_in[13];
    const float* b4   = (const float*)d_in[14];
    const float* g4   = (const float*)d_in[15];
    const float* be4  = (const float*)d_in[16];
    const float* T    = (const float*)d_in[17];
    const float* fc_w = (const float*)d_in[18];
    const float* fc_b = (const float*)d_in[19];

    float* out  = (float*)d_out;
    float* feat = out;                    // (256, 4096)
    float* y    = out + 256*4096;         // (256, 1000)

    conv1_kernel<<<dim3(64, 256), 256>>>(x, w1, b1, g1, be1);
    conv2_kernel<<<dim3(8, 256), 256>>>(w2, b2, g2, be2);
    conv3_kernel<<<dim3(4, 256), 256>>>(w3, b3, g3, be3);
    conv4_kernel<<<dim3(2, 256), 256>>>(w4, b4, g4, be4, feat);
    gemmM_kernel<<<dim3(50, 4), 256>>>(feat, T);
    ob_kernel<<<dim3(64, 256), 256>>>();
    fc_kernel<<<dim3(16, 4), 256>>>(feat, fc_w, fc_b, y);
}

// round 15
// speedup vs baseline: 1.0911x; 1.0911x over previous
#include <cuda_runtime.h>

#define EPS 1e-5f

// ---------------- scratch (device globals; no allocations allowed) ----------
static __device__ float g_act1[256*64*32*32];   // 64 MB
static __device__ float g_act2[256*128*16*16];  // 32 MB
static __device__ float g_act3[256*256*8*8];    // 16 MB
static __device__ float g_M[256*64*50];         // 3.3 MB
static __device__ float g_ob[256*64];

__device__ __forceinline__ float lrelu(float v) { return v >= 0.f ? v : 0.2f*v; }

// ============================================================================
// conv1: x(256,3,64,64) * w1(64,3,5,5) s2 p2 -> (256,64,32,32), IN + lrelu
// NEW: block = (8 c_outs, n), 256 thr; thread = (oy, 4-px seg) x 8 c_outs.
// All 3 channels staged once; weights broadcast; shfl-based IN reduction.
// ============================================================================
__global__ void __launch_bounds__(256) conv1_kernel(
    const float* __restrict__ x, const float* __restrict__ w,
    const float* __restrict__ b, const float* __restrict__ g,
    const float* __restrict__ be)
{
    const int c0 = blockIdx.x * 8;            // gridDim.x = 8
    const int n  = blockIdx.y;
    const int tid = threadIdx.x;              // 256
    const int oy  = tid >> 3;                 // 0..31 output row
    const int seg = tid & 7;                  // 4-px segment
    const int wid = tid >> 5, lane = tid & 31;

    __shared__ __align__(16) float s_in[3*68*69];   // 3 ch, 68 rows, stride 69
    __shared__ float s_w[600];                      // 8 couts x 75
    __shared__ float s_rv[64], s_rq[64];
    __shared__ float s_sc[8], s_sh[8];

    for (int idx = tid; idx < 600; idx += 256) {
        int clo = idx / 75;
        int r   = idx - clo*75;
        s_w[idx] = w[(c0 + clo)*75 + r];
    }
    for (int idx = tid; idx < 3*4624; idx += 256) {
        int c = idx / 4624;
        int r = idx - c*4624;
        int iy = r / 68;
        int ix = r - iy*68;
        float v = 0.f;
        int gy = iy - 2, gx = ix - 2;
        if (gy >= 0 && gy < 64 && gx >= 0 && gx < 64)
            v = x[((n*3 + c) << 12) + (gy << 6) + gx];
        s_in[c*4692 + iy*69 + ix] = v;
    }
    __syncthreads();

    float acc[8][4];
    #pragma unroll
    for (int u = 0; u < 8; ++u)
        #pragma unroll
        for (int p = 0; p < 4; ++p) acc[u][p] = 0.f;

    #pragma unroll
    for (int ch = 0; ch < 3; ++ch) {
        #pragma unroll
        for (int ky = 0; ky < 5; ++ky) {
            const float* row = s_in + ch*4692 + (2*oy + ky)*69 + seg*8;
            float r[11];
            #pragma unroll
            for (int j = 0; j < 11; ++j) r[j] = row[j];
            #pragma unroll
            for (int kx = 0; kx < 5; ++kx) {
                #pragma unroll
                for (int u = 0; u < 8; ++u) {
                    float wv = s_w[u*75 + ch*25 + ky*5 + kx];
                    #pragma unroll
                    for (int p = 0; p < 4; ++p)
                        acc[u][p] += r[2*p + kx] * wv;
                }
            }
        }
    }

    // IN: block-wide reduction per cout via shfl + 8-warp combine
    float lv[8], lq[8];
    #pragma unroll
    for (int u = 0; u < 8; ++u) {
        float bc = b[c0 + u];
        lv[u] = 0.f; lq[u] = 0.f;
        #pragma unroll
        for (int p = 0; p < 4; ++p) {
            acc[u][p] += bc; lv[u] += acc[u][p]; lq[u] += acc[u][p]*acc[u][p];
        }
        #pragma unroll
        for (int off = 16; off >= 1; off >>= 1) {
            lv[u] += __shfl_xor_sync(0xffffffffu, lv[u], off);
            lq[u] += __shfl_xor_sync(0xffffffffu, lq[u], off);
        }
    }
    if (lane == 0) {
        #pragma unroll
        for (int u = 0; u < 8; ++u) { s_rv[wid*8 + u] = lv[u]; s_rq[wid*8 + u] = lq[u]; }
    }
    __syncthreads();
    if (tid < 8) {
        float sv = 0.f, sq = 0.f;
        #pragma unroll
        for (int wq = 0; wq < 8; ++wq) { sv += s_rv[wq*8 + tid]; sq += s_rq[wq*8 + tid]; }
        float mean = sv * (1.f/1024.f);
        float var  = fmaxf(sq * (1.f/1024.f) - mean*mean, 0.f);
        float scale = g[c0 + tid] * rsqrtf(var + EPS);
        s_sc[tid] = scale;
        s_sh[tid] = be[c0 + tid] - mean*scale;
    }
    __syncthreads();
    #pragma unroll
    for (int u = 0; u < 8; ++u) {
        float scale = s_sc[u], shift = s_sh[u];
        float4 o;
        o.x = lrelu(acc[u][0]*scale + shift);
        o.y = lrelu(acc[u][1]*scale + shift);
        o.z = lrelu(acc[u][2]*scale + shift);
        o.w = lrelu(acc[u][3]*scale + shift);
        *(float4*)(g_act1 + ((n*64 + c0 + u) << 10) + oy*32 + seg*4) = o;
    }
}

// ============================================================================
// conv2: act1(256,64,32,32) * w2(128,64,5,5) s2 p2 -> (256,128,16,16), IN+lrelu
// (R13 scalar — known good)
// ============================================================================
__global__ void __launch_bounds__(128) conv2_kernel(
    const float* __restrict__ w, const float* __restrict__ b,
    const float* __restrict__ g, const float* __restrict__ be)
{
    const int c0 = blockIdx.x * 16;
    const int n  = blockIdx.y;
    const int tid  = threadIdx.x;
    const int wid  = tid >> 5;
    const int lane = tid & 31;
    const int oy   = lane >> 1;
    const int seg  = lane & 1;

    __shared__ float s_in[4*36*37];
    __shared__ float s_w[16*100];

    float acc[4][8];
    #pragma unroll
    for (int u = 0; u < 4; ++u)
        #pragma unroll
        for (int p = 0; p < 8; ++p) acc[u][p] = 0.f;

    const float* inbase = g_act1 + ((n*64) << 10);

    for (int cc = 0; cc < 64; cc += 4) {
        __syncthreads();
        for (int idx = tid; idx < 1600; idx += 128) {
            int clo = idx / 100;
            int r   = idx - clo*100;
            s_w[idx] = w[(c0 + clo)*1600 + cc*25 + r];
        }
        for (int idx = tid; idx < 5184; idx += 128) {
            int ch = idx / 1296;
            int r  = idx - ch*1296;
            int iy = r / 36;
            int ix = r - iy*36;
            float v = 0.f;
            int gy = iy - 2, gx = ix - 2;
            if (gy >= 0 && gy < 32 && gx >= 0 && gx < 32)
                v = inbase[((cc + ch) << 10) + (gy << 5) + gx];
            s_in[ch*1332 + iy*37 + ix] = v;
        }
        __syncthreads();
        #pragma unroll
        for (int ch = 0; ch < 4; ++ch) {
            const float* sw = s_w + (wid*4)*100 + ch*25;
            const float* si = s_in + ch*1332 + seg*16;
            #pragma unroll
            for (int ky = 0; ky < 5; ++ky) {
                const float* row = si + (2*oy + ky)*37;
                float r[19];
                #pragma unroll
                for (int j = 0; j < 19; ++j) r[j] = row[j];
                #pragma unroll
                for (int kx = 0; kx < 5; ++kx) {
                    float wv[4];
                    #pragma unroll
                    for (int u = 0; u < 4; ++u) wv[u] = sw[u*100 + ky*5 + kx];
                    #pragma unroll
                    for (int u = 0; u < 4; ++u)
                        #pragma unroll
                        for (int p = 0; p < 8; ++p)
                            acc[u][p] += r[2*p + kx] * wv[u];
                }
            }
        }
    }

    #pragma unroll
    for (int u = 0; u < 4; ++u) {
        int co = c0 + wid*4 + u;
        float bc = b[co];
        float lv = 0.f, lq = 0.f;
        #pragma unroll
        for (int p = 0; p < 8; ++p) {
            acc[u][p] += bc; lv += acc[u][p]; lq += acc[u][p]*acc[u][p];
        }
        #pragma unroll
        for (int off = 16; off >= 1; off >>= 1) {
            lv += __shfl_xor_sync(0xffffffffu, lv, off);
            lq += __shfl_xor_sync(0xffffffffu, lq, off);
        }
        float mean = lv * (1.f/256.f);
        float var  = fmaxf(lq * (1.f/256.f) - mean*mean, 0.f);
        float scale = g[co] * rsqrtf(var + EPS);
        float shift = be[co] - mean*scale;
        float* p0 = g_act2 + ((n*128 + co) << 8) + oy*16 + seg*8;
        float4 o0, o1;
        o0.x = lrelu(acc[u][0]*scale + shift); o0.y = lrelu(acc[u][1]*scale + shift);
        o0.z = lrelu(acc[u][2]*scale + shift); o0.w = lrelu(acc[u][3]*scale + shift);
        o1.x = lrelu(acc[u][4]*scale + shift); o1.y = lrelu(acc[u][5]*scale + shift);
        o1.z = lrelu(acc[u][6]*scale + shift); o1.w = lrelu(acc[u][7]*scale + shift);
        *(float4*)(p0)     = o0;
        *(float4*)(p0 + 4) = o1;
    }
}

// ============================================================================
// conv3: act2(256,128,16,16) * w3(256,128,5,5) s2 p2 -> (256,256,8,8), IN+lrelu
// (R13 scalar — known good)
// ============================================================================
__global__ void __launch_bounds__(128) conv3_kernel(
    const float* __restrict__ w, const float* __restrict__ b,
    const float* __restrict__ g, const float* __restrict__ be)
{
    const int c0 = blockIdx.x * 64;
    const int n  = blockIdx.y;
    const int tid = threadIdx.x;
    const int grp = tid >> 3;
    const int oy  = tid & 7;

    __shared__ float s_in[4*20*21];
    __shared__ float s_w[64*101];

    float acc[4][8];
    #pragma unroll
    for (int u = 0; u < 4; ++u)
        #pragma unroll
        for (int p = 0; p < 8; ++p) acc[u][p] = 0.f;

    const float* inbase = g_act2 + ((n*128) << 8);

    for (int cc = 0; cc < 128; cc += 4) {
        __syncthreads();
        for (int idx = tid; idx < 6400; idx += 128) {
            int clo = idx / 100;
            int r   = idx - clo*100;
            s_w[clo*101 + r] = w[(c0 + clo)*3200 + cc*25 + r];
        }
        for (int idx = tid; idx < 1600; idx += 128) {
            int ch = idx / 400;
            int r  = idx - ch*400;
            int iy = r / 20;
            int ix = r - iy*20;
            float v = 0.f;
            int gy = iy - 2, gx = ix - 2;
            if (gy >= 0 && gy < 16 && gx >= 0 && gx < 16)
                v = inbase[((cc + ch) << 8) + (gy << 4) + gx];
            s_in[ch*420 + iy*21 + ix] = v;
        }
        __syncthreads();
        #pragma unroll
        for (int ch = 0; ch < 4; ++ch) {
            const float* sw = s_w + (grp*4)*101 + ch*25;
            const float* si = s_in + ch*420;
            #pragma unroll
            for (int ky = 0; ky < 5; ++ky) {
                const float* row = si + (2*oy + ky)*21;
                float r[19];
                #pragma unroll
                for (int j = 0; j < 19; ++j) r[j] = row[j];
                #pragma unroll
                for (int kx = 0; kx < 5; ++kx) {
                    float wv[4];
                    #pragma unroll
                    for (int u = 0; u < 4; ++u) wv[u] = sw[u*101 + ky*5 + kx];
                    #pragma unroll
                    for (int u = 0; u < 4; ++u)
                        #pragma unroll
                        for (int p = 0; p < 8; ++p)
                            acc[u][p] += r[2*p + kx] * wv[u];
                }
            }
        }
    }

    #pragma unroll
    for (int u = 0; u < 4; ++u) {
        int co = c0 + grp*4 + u;
        float bc = b[co];
        float lv = 0.f, lq = 0.f;
        #pragma unroll
        for (int p = 0; p < 8; ++p) {
            acc[u][p] += bc; lv += acc[u][p]; lq += acc[u][p]*acc[u][p];
        }
        #pragma unroll
        for (int off = 4; off >= 1; off >>= 1) {
            lv += __shfl_xor_sync(0xffffffffu, lv, off);
            lq += __shfl_xor_sync(0xffffffffu, lq, off);
        }
        float mean = lv * (1.f/64.f);
        float var  = fmaxf(lq * (1.f/64.f) - mean*mean, 0.f);
        float scale = g[co] * rsqrtf(var + EPS);
        float shift = be[co] - mean*scale;
        float* p0 = g_act3 + ((n*256 + co) << 6) + oy*8;
        float4 o0, o1;
        o0.x = lrelu(acc[u][0]*scale + shift); o0.y = lrelu(acc[u][1]*scale + shift);
        o0.z = lrelu(acc[u][2]*scale + shift); o0.w = lrelu(acc[u][3]*scale + shift);
        o1.x = lrelu(acc[u][4]*scale + shift); o1.y = lrelu(acc[u][5]*scale + shift);
        o1.z = lrelu(acc[u][6]*scale + shift); o1.w = lrelu(acc[u][7]*scale + shift);
        *(float4*)(p0)     = o0;
        *(float4*)(p0 + 4) = o1;
    }
}

// ============================================================================
// conv4: R13 structure + structured (div/mod-free, vectorized) weight staging.
// ============================================================================
__global__ void __launch_bounds__(256) conv4_kernel(
    const float* __restrict__ w, const float* __restrict__ b,
    const float* __restrict__ g, const float* __restrict__ be,
    float* __restrict__ feat)
{
    const int c0   = blockIdx.x * 128;        // gridDim.x = 2
    const int n    = blockIdx.y;
    const int tid  = threadIdx.x;             // 256
    const int half = tid >> 7;                // ch half
    const int sid  = tid & 127;
    const int grp  = sid >> 2;                // 0..31 -> couts c0+grp*4+u
    const int oy   = sid & 3;                 // output row

    __shared__ float s_in[2][4*110];
    __shared__ float s_w[2][128*37];
    __shared__ float s_m[128*17];

    float acc[4][4];
    #pragma unroll
    for (int u = 0; u < 4; ++u)
        #pragma unroll
        for (int p = 0; p < 4; ++p) acc[u][p] = 0.f;

    const float* inbase = g_act3 + ((n*256) << 6) + (half << 13);
    const int wchbase = half*128;
    const float* wp = w + (c0 + sid)*2304 + wchbase*9;   // this thread's cout row

    for (int cc = 0; cc < 128; cc += 4) {
        __syncthreads();
        for (int idx = sid; idx < 440; idx += 128) {
            int ch = idx / 110;
            int r  = idx - ch*110;
            int iy = r / 11;
            int ix = r - iy*11;
            float v = 0.f;
            int gy = iy - 1, gx = ix - 1;
            if (gy >= 0 && gy < 8 && gx >= 0 && gx < 8)
                v = inbase[((cc + ch) << 6) + (gy << 3) + gx];
            s_in[half][ch*110 + iy*11 + ix] = v;
        }
        {   // structured weight staging: thread sid owns cout c0+sid
            const float4* ws4 = (const float4*)(wp + cc*9);   // 36 floats, 16B-aligned
            float* sd = s_w[half] + sid*37;
            #pragma unroll
            for (int r4 = 0; r4 < 9; ++r4) {
                float4 v = ws4[r4];
                sd[r4*4+0] = v.x; sd[r4*4+1] = v.y;
                sd[r4*4+2] = v.z; sd[r4*4+3] = v.w;
            }
        }
        __syncthreads();
        #pragma unroll
        for (int ch = 0; ch < 4; ++ch) {
            const float* si = s_in[half] + ch*110;
            float rr[3][9];
            #pragma unroll
            for (int ky = 0; ky < 3; ++ky) {
                const float* row = si + (2*oy + ky)*11;
                #pragma unroll
                for (int j = 0; j < 9; ++j) rr[ky][j] = row[j];
            }
            const float* sw = s_w[half] + (grp*4)*37 + ch*9;
            #pragma unroll
            for (int ky = 0; ky < 3; ++ky) {
                #pragma unroll
                for (int kx = 0; kx < 3; ++kx) {
                    float wv[4];
                    #pragma unroll
                    for (int u = 0; u < 4; ++u) wv[u] = sw[u*37 + ky*3 + kx];
                    #pragma unroll
                    for (int u = 0; u < 4; ++u)
                        #pragma unroll
                        for (int p = 0; p < 4; ++p)
                            acc[u][p] += rr[ky][2*p + kx] * wv[u];
                }
            }
        }
    }

    __syncthreads();
    if (half == 1) {
        #pragma unroll
        for (int u = 0; u < 4; ++u)
            #pragma unroll
            for (int p = 0; p < 4; ++p)
                s_m[sid*17 + u*4 + p] = acc[u][p];
    }
    __syncthreads();
    if (half == 0) {
        #pragma unroll
        for (int u = 0; u < 4; ++u)
            #pragma unroll
            for (int p = 0; p < 4; ++p)
                acc[u][p] += s_m[sid*17 + u*4 + p];

        #pragma unroll
        for (int u = 0; u < 4; ++u) {
            int co = c0 + grp*4 + u;
            float bc = b[co];
            float lv = 0.f, lq = 0.f;
            #pragma unroll
            for (int p = 0; p < 4; ++p) {
                acc[u][p] += bc; lv += acc[u][p]; lq += acc[u][p]*acc[u][p];
            }
            #pragma unroll
            for (int off = 2; off >= 1; off >>= 1) {
                lv += __shfl_xor_sync(0xffffffffu, lv, off);
                lq += __shfl_xor_sync(0xffffffffu, lq, off);
            }
            float mean = lv * (1.f/16.f);
            float var  = fmaxf(lq * (1.f/16.f) - mean*mean, 0.f);
            float scale = g[co] * rsqrtf(var + EPS);
            float shift = be[co] - mean*scale;
            float4 o;
            o.x = lrelu(acc[u][0]*scale + shift); o.y = lrelu(acc[u][1]*scale + shift);
            o.z = lrelu(acc[u][2]*scale + shift); o.w = lrelu(acc[u][3]*scale + shift);
            *(float4*)(feat + n*4096 + (co << 4) + oy*4) = o;
        }
    }
}

// ============================================================================
// M = feat(256x4096) @ T(4096x3200), register-prefetch (unchanged)
// ============================================================================
__global__ void __launch_bounds__(256) gemmM_kernel(
    const float* __restrict__ A, const float* __restrict__ B)
{
    const int n0 = blockIdx.x * 64;
    const int m0 = blockIdx.y * 64;
    const int tid = threadIdx.x;
    const int tx = tid & 15, ty = tid >> 4;

    __shared__ float sA[16*65];
    __shared__ float sB[16*64];

    float acc[4][4];
    #pragma unroll
    for (int i = 0; i < 4; ++i)
        #pragma unroll
        for (int j = 0; j < 4; ++j) acc[i][j] = 0.f;

    const int lrow = tid >> 2;
    const int lkk  = (tid & 3) << 2;
    const int bk   = tid >> 4;
    const int bj   = (tid & 15) << 2;

    float4 va = *(const float4*)(A + (m0 + lrow)*4096 + lkk);
    float4 vb = *(const float4*)(B + bk*3200 + n0 + bj);

    for (int kt = 0; kt < 4096; kt += 16) {
        sA[(lkk+0)*65 + lrow] = va.x;
        sA[(lkk+1)*65 + lrow] = va.y;
        sA[(lkk+2)*65 + lrow] = va.z;
        sA[(lkk+3)*65 + lrow] = va.w;
        *(float4*)(sB + bk*64 + bj) = vb;
        __syncthreads();
        if (kt + 16 < 4096) {
            va = *(const float4*)(A + (m0 + lrow)*4096 + kt + 16 + lkk);
            vb = *(const float4*)(B + (kt + 16 + bk)*3200 + n0 + bj);
        }
        #pragma unroll
        for (int k = 0; k < 16; ++k) {
            float a[4], bb[4];
            #pragma unroll
            for (int i = 0; i < 4; ++i) a[i]  = sA[k*65 + ty*4 + i];
            #pragma unroll
            for (int j = 0; j < 4; ++j) bb[j] = sB[k*64 + tx*4 + j];
            #pragma unroll
            for (int i = 0; i < 4; ++i)
                #pragma unroll
                for (int j = 0; j < 4; ++j) acc[i][j] += a[i]*bb[j];
        }
        __syncthreads();
    }
    #pragma unroll
    for (int i = 0; i < 4; ++i)
        #pragma unroll
        for (int j = 0; j < 4; ++j)
            g_M[(m0 + ty*4 + i)*3200 + n0 + tx*4 + j] = acc[i][j];
}

// ============================================================================
// o_b: NEW — one block per j; M[j] row staged once; loop o with shfl reduce.
// o_b[j,o] = sum_i exp(-sum_k |M[i,o,k]-M[j,o,k]|) - 1
// ============================================================================
__global__ void __launch_bounds__(256) ob_kernel()
{
    const int j = blockIdx.x;       // 0..255
    const int i = threadIdx.x;      // 0..255 (= row i)

    __shared__ __align__(16) float s_mj[3200];
    __shared__ float s_part[8];

    for (int k = i; k < 3200; k += 256) s_mj[k] = g_M[j*3200 + k];
    __syncthreads();

    const float* mi = g_M + i*3200;
    for (int o = 0; o < 64; ++o) {
        const float2* a2 = (const float2*)(mi + o*50);
        const float2* b2 = (const float2*)(s_mj + o*50);
        float d = 0.f;
        #pragma unroll
        for (int k = 0; k < 25; ++k) {
            float2 a = a2[k], bq = b2[k];
            d += fabsf(a.x - bq.x) + fabsf(a.y - bq.y);
        }
        float e = expf(-d);
        #pragma unroll
        for (int off = 16; off >= 1; off >>= 1)
            e += __shfl_xor_sync(0xffffffffu, e, off);
        if ((i & 31) == 0) s_part[i >> 5] = e;
        __syncthreads();
        if (i == 0) {
            float s = 0.f;
            #pragma unroll
            for (int wq = 0; wq < 8; ++wq) s += s_part[wq];
            g_ob[j*64 + o] = s - 1.0f;
        }
        __syncthreads();
    }
}

// ============================================================================
// y = [feat | o_b] @ fc_w^T + fc_b (unchanged)
// ============================================================================
__global__ void __launch_bounds__(256) fc_kernel(
    const float* __restrict__ feat, const float* __restrict__ Wt,
    const float* __restrict__ bias, float* __restrict__ y)
{
    const int n0 = blockIdx.x * 64;
    const int m0 = blockIdx.y * 64;
    const int tid = threadIdx.x;
    const int tx = tid & 15, ty = tid >> 4;

    __shared__ float sA[16*65];
    __shared__ float sB[16*65];

    float acc[4][4];
    #pragma unroll
    for (int i = 0; i < 4; ++i)
        #pragma unroll
        for (int j = 0; j < 4; ++j) acc[i][j] = 0.f;

    const int lrow = tid >> 2;
    const int lkk  = (tid & 3) << 2;
    const bool bvalid = (n0 + lrow) < 1000;

    float4 va = *(const float4*)(feat + (m0 + lrow)*4096 + lkk);
    float4 vb = bvalid ? *(const float4*)(Wt + (n0 + lrow)*4160 + lkk)
                       : make_float4(0.f, 0.f, 0.f, 0.f);

    for (int kt = 0; kt < 4160; kt += 16) {
        sA[(lkk+0)*65 + lrow] = va.x;
        sA[(lkk+1)*65 + lrow] = va.y;
        sA[(lkk+2)*65 + lrow] = va.z;
        sA[(lkk+3)*65 + lrow] = va.w;
        sB[(lkk+0)*65 + lrow] = vb.x;
        sB[(lkk+1)*65 + lrow] = vb.y;
        sB[(lkk+2)*65 + lrow] = vb.z;
        sB[(lkk+3)*65 + lrow] = vb.w;
        __syncthreads();
        int knext = kt + 16;
        if (knext < 4160) {
            va = (knext < 4096)
               ? *(const float4*)(feat + (m0 + lrow)*4096 + knext + lkk)
               : *(const float4*)(g_ob + (m0 + lrow)*64 + (knext - 4096) + lkk);
            vb = bvalid ? *(const float4*)(Wt + (n0 + lrow)*4160 + knext + lkk)
                        : make_float4(0.f, 0.f, 0.f, 0.f);
        }
        #pragma unroll
        for (int k = 0; k < 16; ++k) {
            float a[4], bb[4];
            #pragma unroll
            for (int i = 0; i < 4; ++i) a[i]  = sA[k*65 + ty*4 + i];
            #pragma unroll
            for (int j = 0; j < 4; ++j) bb[j] = sB[k*65 + tx*4 + j];
            #pragma unroll
            for (int i = 0; i < 4; ++i)
                #pragma unroll
                for (int j = 0; j < 4; ++j) acc[i][j] += a[i]*bb[j];
        }
        __syncthreads();
    }
    #pragma unroll
    for (int i = 0; i < 4; ++i) {
        #pragma unroll
        for (int j = 0; j < 4; ++j) {
            int nn = n0 + tx*4 + j;
            if (nn < 1000)
                y[(m0 + ty*4 + i)*1000 + nn] = acc[i][j] + bias[nn];
        }
    }
}

// ============================================================================
extern "C" void kernel_launch(void* const* d_in, const int* in_sizes, int n_in,
                              void* d_out, int out_size)
{
    (void)in_sizes; (void)n_in; (void)out_size;
    const float* x    = (const float*)d_in[0];
    const float* w1   = (const float*)d_in[1];
    const float* b1   = (const float*)d_in[2];
    const float* g1   = (const float*)d_in[3];
    const float* be1  = (const float*)d_in[4];
    const float* w2   = (const float*)d_in[5];
    const float* b2   = (const float*)d_in[6];
    const float* g2   = (const float*)d_in[7];
    const float* be2  = (const float*)d_in[8];
    const float* w3   = (const float*)d_in[9];
    const float* b3   = (const float*)d_in[10];
    const float* g3   = (const float*)d_in[11];
    const float* be3  = (const float*)d_in[12];
    const float* w4   = (const float*)d_in[13];
    const float* b4   = (const float*)d_in[14];
    const float* g4   = (const float*)d_in[15];
    const float* be4  = (const float*)d_in[16];
    const float* T    = (const float*)d_in[17];
    const float* fc_w = (const float*)d_in[18];
    const float* fc_b = (const float*)d_in[19];

    float* out  = (float*)d_out;
    float* feat = out;                    // (256, 4096)
    float* y    = out + 256*4096;         // (256, 1000)

    conv1_kernel<<<dim3(8, 256), 256>>>(x, w1, b1, g1, be1);
    conv2_kernel<<<dim3(8, 256), 128>>>(w2, b2, g2, be2);
    conv3_kernel<<<dim3(4, 256), 128>>>(w3, b3, g3, be3);
    conv4_kernel<<<dim3(2, 256), 256>>>(w4, b4, g4, be4, feat);
    gemmM_kernel<<<dim3(50, 4), 256>>>(feat, T);
    ob_kernel<<<256, 256>>>();
    fc_kernel<<<dim3(16, 4), 256>>>(feat, fc_w, fc_b, y);
}

// round 16
// speedup vs baseline: 1.0936x; 1.0023x over previous
#include <cuda_runtime.h>

#define EPS 1e-5f

// ---------------- scratch (device globals; no allocations allowed) ----------
static __device__ float g_act1[256*64*32*32];   // 64 MB
static __device__ float g_act2[256*128*16*16];  // 32 MB
static __device__ float g_act3[256*256*8*8];    // 16 MB
static __device__ float g_M[256*64*50];         // 3.3 MB
static __device__ float g_ob[256*64];

__device__ __forceinline__ float lrelu(float v) { return v >= 0.f ? v : 0.2f*v; }

// ============================================================================
// conv1: x(256,3,64,64) * w1(64,3,5,5) s2 p2 -> (256,64,32,32), IN + lrelu
// NEW: block = (8 c_outs, n), 256 thr; thread = (oy, 4-px seg) x 8 c_outs.
// All 3 channels staged once; weights broadcast; shfl-based IN reduction.
// ============================================================================
__global__ void __launch_bounds__(256) conv1_kernel(
    const float* __restrict__ x, const float* __restrict__ w,
    const float* __restrict__ b, const float* __restrict__ g,
    const float* __restrict__ be)
{
    const int c0 = blockIdx.x * 8;            // gridDim.x = 8
    const int n  = blockIdx.y;
    const int tid = threadIdx.x;              // 256
    const int oy  = tid >> 3;                 // 0..31 output row
    const int seg = tid & 7;                  // 4-px segment
    const int wid = tid >> 5, lane = tid & 31;

    __shared__ __align__(16) float s_in[3*68*69];   // 3 ch, 68 rows, stride 69
    __shared__ float s_w[600];                      // 8 couts x 75
    __shared__ float s_rv[64], s_rq[64];
    __shared__ float s_sc[8], s_sh[8];

    for (int idx = tid; idx < 600; idx += 256) {
        int clo = idx / 75;
        int r   = idx - clo*75;
        s_w[idx] = w[(c0 + clo)*75 + r];
    }
    for (int idx = tid; idx < 3*4624; idx += 256) {
        int c = idx / 4624;
        int r = idx - c*4624;
        int iy = r / 68;
        int ix = r - iy*68;
        float v = 0.f;
        int gy = iy - 2, gx = ix - 2;
        if (gy >= 0 && gy < 64 && gx >= 0 && gx < 64)
            v = x[((n*3 + c) << 12) + (gy << 6) + gx];
        s_in[c*4692 + iy*69 + ix] = v;
    }
    __syncthreads();

    float acc[8][4];
    #pragma unroll
    for (int u = 0; u < 8; ++u)
        #pragma unroll
        for (int p = 0; p < 4; ++p) acc[u][p] = 0.f;

    #pragma unroll
    for (int ch = 0; ch < 3; ++ch) {
        #pragma unroll
        for (int ky = 0; ky < 5; ++ky) {
            const float* row = s_in + ch*4692 + (2*oy + ky)*69 + seg*8;
            float r[11];
            #pragma unroll
            for (int j = 0; j < 11; ++j) r[j] = row[j];
            #pragma unroll
            for (int kx = 0; kx < 5; ++kx) {
                #pragma unroll
                for (int u = 0; u < 8; ++u) {
                    float wv = s_w[u*75 + ch*25 + ky*5 + kx];
                    #pragma unroll
                    for (int p = 0; p < 4; ++p)
                        acc[u][p] += r[2*p + kx] * wv;
                }
            }
        }
    }

    // IN: block-wide reduction per cout via shfl + 8-warp combine
    float lv[8], lq[8];
    #pragma unroll
    for (int u = 0; u < 8; ++u) {
        float bc = b[c0 + u];
        lv[u] = 0.f; lq[u] = 0.f;
        #pragma unroll
        for (int p = 0; p < 4; ++p) {
            acc[u][p] += bc; lv[u] += acc[u][p]; lq[u] += acc[u][p]*acc[u][p];
        }
        #pragma unroll
        for (int off = 16; off >= 1; off >>= 1) {
            lv[u] += __shfl_xor_sync(0xffffffffu, lv[u], off);
            lq[u] += __shfl_xor_sync(0xffffffffu, lq[u], off);
        }
    }
    if (lane == 0) {
        #pragma unroll
        for (int u = 0; u < 8; ++u) { s_rv[wid*8 + u] = lv[u]; s_rq[wid*8 + u] = lq[u]; }
    }
    __syncthreads();
    if (tid < 8) {
        float sv = 0.f, sq = 0.f;
        #pragma unroll
        for (int wq = 0; wq < 8; ++wq) { sv += s_rv[wq*8 + tid]; sq += s_rq[wq*8 + tid]; }
        float mean = sv * (1.f/1024.f);
        float var  = fmaxf(sq * (1.f/1024.f) - mean*mean, 0.f);
        float scale = g[c0 + tid] * rsqrtf(var + EPS);
        s_sc[tid] = scale;
        s_sh[tid] = be[c0 + tid] - mean*scale;
    }
    __syncthreads();
    #pragma unroll
    for (int u = 0; u < 8; ++u) {
        float scale = s_sc[u], shift = s_sh[u];
        float4 o;
        o.x = lrelu(acc[u][0]*scale + shift);
        o.y = lrelu(acc[u][1]*scale + shift);
        o.z = lrelu(acc[u][2]*scale + shift);
        o.w = lrelu(acc[u][3]*scale + shift);
        *(float4*)(g_act1 + ((n*64 + c0 + u) << 10) + oy*32 + seg*4) = o;
    }
}

// ============================================================================
// conv2: act1(256,64,32,32) * w2(128,64,5,5) s2 p2 -> (256,128,16,16), IN+lrelu
// (R13 scalar — known good)
// ============================================================================
__global__ void __launch_bounds__(128) conv2_kernel(
    const float* __restrict__ w, const float* __restrict__ b,
    const float* __restrict__ g, const float* __restrict__ be)
{
    const int c0 = blockIdx.x * 16;
    const int n  = blockIdx.y;
    const int tid  = threadIdx.x;
    const int wid  = tid >> 5;
    const int lane = tid & 31;
    const int oy   = lane >> 1;
    const int seg  = lane & 1;

    __shared__ float s_in[4*36*37];
    __shared__ float s_w[16*100];

    float acc[4][8];
    #pragma unroll
    for (int u = 0; u < 4; ++u)
        #pragma unroll
        for (int p = 0; p < 8; ++p) acc[u][p] = 0.f;

    const float* inbase = g_act1 + ((n*64) << 10);

    for (int cc = 0; cc < 64; cc += 4) {
        __syncthreads();
        for (int idx = tid; idx < 1600; idx += 128) {
            int clo = idx / 100;
            int r   = idx - clo*100;
            s_w[idx] = w[(c0 + clo)*1600 + cc*25 + r];
        }
        for (int idx = tid; idx < 5184; idx += 128) {
            int ch = idx / 1296;
            int r  = idx - ch*1296;
            int iy = r / 36;
            int ix = r - iy*36;
            float v = 0.f;
            int gy = iy - 2, gx = ix - 2;
            if (gy >= 0 && gy < 32 && gx >= 0 && gx < 32)
                v = inbase[((cc + ch) << 10) + (gy << 5) + gx];
            s_in[ch*1332 + iy*37 + ix] = v;
        }
        __syncthreads();
        #pragma unroll
        for (int ch = 0; ch < 4; ++ch) {
            const float* sw = s_w + (wid*4)*100 + ch*25;
            const float* si = s_in + ch*1332 + seg*16;
            #pragma unroll
            for (int ky = 0; ky < 5; ++ky) {
                const float* row = si + (2*oy + ky)*37;
                float r[19];
                #pragma unroll
                for (int j = 0; j < 19; ++j) r[j] = row[j];
                #pragma unroll
                for (int kx = 0; kx < 5; ++kx) {
                    float wv[4];
                    #pragma unroll
                    for (int u = 0; u < 4; ++u) wv[u] = sw[u*100 + ky*5 + kx];
                    #pragma unroll
                    for (int u = 0; u < 4; ++u)
                        #pragma unroll
                        for (int p = 0; p < 8; ++p)
                            acc[u][p] += r[2*p + kx] * wv[u];
                }
            }
        }
    }

    #pragma unroll
    for (int u = 0; u < 4; ++u) {
        int co = c0 + wid*4 + u;
        float bc = b[co];
        float lv = 0.f, lq = 0.f;
        #pragma unroll
        for (int p = 0; p < 8; ++p) {
            acc[u][p] += bc; lv += acc[u][p]; lq += acc[u][p]*acc[u][p];
        }
        #pragma unroll
        for (int off = 16; off >= 1; off >>= 1) {
            lv += __shfl_xor_sync(0xffffffffu, lv, off);
            lq += __shfl_xor_sync(0xffffffffu, lq, off);
        }
        float mean = lv * (1.f/256.f);
        float var  = fmaxf(lq * (1.f/256.f) - mean*mean, 0.f);
        float scale = g[co] * rsqrtf(var + EPS);
        float shift = be[co] - mean*scale;
        float* p0 = g_act2 + ((n*128 + co) << 8) + oy*16 + seg*8;
        float4 o0, o1;
        o0.x = lrelu(acc[u][0]*scale + shift); o0.y = lrelu(acc[u][1]*scale + shift);
        o0.z = lrelu(acc[u][2]*scale + shift); o0.w = lrelu(acc[u][3]*scale + shift);
        o1.x = lrelu(acc[u][4]*scale + shift); o1.y = lrelu(acc[u][5]*scale + shift);
        o1.z = lrelu(acc[u][6]*scale + shift); o1.w = lrelu(acc[u][7]*scale + shift);
        *(float4*)(p0)     = o0;
        *(float4*)(p0 + 4) = o1;
    }
}

// ============================================================================
// conv3: act2(256,128,16,16) * w3(256,128,5,5) s2 p2 -> (256,256,8,8), IN+lrelu
// (R13 scalar — known good)
// ============================================================================
__global__ void __launch_bounds__(128) conv3_kernel(
    const float* __restrict__ w, const float* __restrict__ b,
    const float* __restrict__ g, const float* __restrict__ be)
{
    const int c0 = blockIdx.x * 64;
    const int n  = blockIdx.y;
    const int tid = threadIdx.x;
    const int grp = tid >> 3;
    const int oy  = tid & 7;

    __shared__ float s_in[4*20*21];
    __shared__ float s_w[64*101];

    float acc[4][8];
    #pragma unroll
    for (int u = 0; u < 4; ++u)
        #pragma unroll
        for (int p = 0; p < 8; ++p) acc[u][p] = 0.f;

    const float* inbase = g_act2 + ((n*128) << 8);

    for (int cc = 0; cc < 128; cc += 4) {
        __syncthreads();
        for (int idx = tid; idx < 6400; idx += 128) {
            int clo = idx / 100;
            int r   = idx - clo*100;
            s_w[clo*101 + r] = w[(c0 + clo)*3200 + cc*25 + r];
        }
        for (int idx = tid; idx < 1600; idx += 128) {
            int ch = idx / 400;
            int r  = idx - ch*400;
            int iy = r / 20;
            int ix = r - iy*20;
            float v = 0.f;
            int gy = iy - 2, gx = ix - 2;
            if (gy >= 0 && gy < 16 && gx >= 0 && gx < 16)
                v = inbase[((cc + ch) << 8) + (gy << 4) + gx];
            s_in[ch*420 + iy*21 + ix] = v;
        }
        __syncthreads();
        #pragma unroll
        for (int ch = 0; ch < 4; ++ch) {
            const float* sw = s_w + (grp*4)*101 + ch*25;
            const float* si = s_in + ch*420;
            #pragma unroll
            for (int ky = 0; ky < 5; ++ky) {
                const float* row = si + (2*oy + ky)*21;
                float r[19];
                #pragma unroll
                for (int j = 0; j < 19; ++j) r[j] = row[j];
                #pragma unroll
                for (int kx = 0; kx < 5; ++kx) {
                    float wv[4];
                    #pragma unroll
                    for (int u = 0; u < 4; ++u) wv[u] = sw[u*101 + ky*5 + kx];
                    #pragma unroll
                    for (int u = 0; u < 4; ++u)
                        #pragma unroll
                        for (int p = 0; p < 8; ++p)
                            acc[u][p] += r[2*p + kx] * wv[u];
                }
            }
        }
    }

    #pragma unroll
    for (int u = 0; u < 4; ++u) {
        int co = c0 + grp*4 + u;
        float bc = b[co];
        float lv = 0.f, lq = 0.f;
        #pragma unroll
        for (int p = 0; p < 8; ++p) {
            acc[u][p] += bc; lv += acc[u][p]; lq += acc[u][p]*acc[u][p];
        }
        #pragma unroll
        for (int off = 4; off >= 1; off >>= 1) {
            lv += __shfl_xor_sync(0xffffffffu, lv, off);
            lq += __shfl_xor_sync(0xffffffffu, lq, off);
        }
        float mean = lv * (1.f/64.f);
        float var  = fmaxf(lq * (1.f/64.f) - mean*mean, 0.f);
        float scale = g[co] * rsqrtf(var + EPS);
        float shift = be[co] - mean*scale;
        float* p0 = g_act3 + ((n*256 + co) << 6) + oy*8;
        float4 o0, o1;
        o0.x = lrelu(acc[u][0]*scale + shift); o0.y = lrelu(acc[u][1]*scale + shift);
        o0.z = lrelu(acc[u][2]*scale + shift); o0.w = lrelu(acc[u][3]*scale + shift);
        o1.x = lrelu(acc[u][4]*scale + shift); o1.y = lrelu(acc[u][5]*scale + shift);
        o1.z = lrelu(acc[u][6]*scale + shift); o1.w = lrelu(acc[u][7]*scale + shift);
        *(float4*)(p0)     = o0;
        *(float4*)(p0 + 4) = o1;
    }
}

// ============================================================================
// conv4: R13 structure + structured (div/mod-free, vectorized) weight staging.
// ============================================================================
__global__ void __launch_bounds__(256) conv4_kernel(
    const float* __restrict__ w, const float* __restrict__ b,
    const float* __restrict__ g, const float* __restrict__ be,
    float* __restrict__ feat)
{
    const int c0   = blockIdx.x * 128;        // gridDim.x = 2
    const int n    = blockIdx.y;
    const int tid  = threadIdx.x;             // 256
    const int half = tid >> 7;                // ch half
    const int sid  = tid & 127;
    const int grp  = sid >> 2;                // 0..31 -> couts c0+grp*4+u
    const int oy   = sid & 3;                 // output row

    __shared__ float s_in[2][4*110];
    __shared__ float s_w[2][128*37];
    __shared__ float s_m[128*17];

    float acc[4][4];
    #pragma unroll
    for (int u = 0; u < 4; ++u)
        #pragma unroll
        for (int p = 0; p < 4; ++p) acc[u][p] = 0.f;

    const float* inbase = g_act3 + ((n*256) << 6) + (half << 13);
    const int wchbase = half*128;
    const float* wp = w + (c0 + sid)*2304 + wchbase*9;   // this thread's cout row

    for (int cc = 0; cc < 128; cc += 4) {
        __syncthreads();
        for (int idx = sid; idx < 440; idx += 128) {
            int ch = idx / 110;
            int r  = idx - ch*110;
            int iy = r / 11;
            int ix = r - iy*11;
            float v = 0.f;
            int gy = iy - 1, gx = ix - 1;
            if (gy >= 0 && gy < 8 && gx >= 0 && gx < 8)
                v = inbase[((cc + ch) << 6) + (gy << 3) + gx];
            s_in[half][ch*110 + iy*11 + ix] = v;
        }
        {   // structured weight staging: thread sid owns cout c0+sid
            const float4* ws4 = (const float4*)(wp + cc*9);   // 36 floats, 16B-aligned
            float* sd = s_w[half] + sid*37;
            #pragma unroll
            for (int r4 = 0; r4 < 9; ++r4) {
                float4 v = ws4[r4];
                sd[r4*4+0] = v.x; sd[r4*4+1] = v.y;
                sd[r4*4+2] = v.z; sd[r4*4+3] = v.w;
            }
        }
        __syncthreads();
        #pragma unroll
        for (int ch = 0; ch < 4; ++ch) {
            const float* si = s_in[half] + ch*110;
            float rr[3][9];
            #pragma unroll
            for (int ky = 0; ky < 3; ++ky) {
                const float* row = si + (2*oy + ky)*11;
                #pragma unroll
                for (int j = 0; j < 9; ++j) rr[ky][j] = row[j];
            }
            const float* sw = s_w[half] + (grp*4)*37 + ch*9;
            #pragma unroll
            for (int ky = 0; ky < 3; ++ky) {
                #pragma unroll
                for (int kx = 0; kx < 3; ++kx) {
                    float wv[4];
                    #pragma unroll
                    for (int u = 0; u < 4; ++u) wv[u] = sw[u*37 + ky*3 + kx];
                    #pragma unroll
                    for (int u = 0; u < 4; ++u)
                        #pragma unroll
                        for (int p = 0; p < 4; ++p)
                            acc[u][p] += rr[ky][2*p + kx] * wv[u];
                }
            }
        }
    }

    __syncthreads();
    if (half == 1) {
        #pragma unroll
        for (int u = 0; u < 4; ++u)
            #pragma unroll
            for (int p = 0; p < 4; ++p)
                s_m[sid*17 + u*4 + p] = acc[u][p];
    }
    __syncthreads();
    if (half == 0) {
        #pragma unroll
        for (int u = 0; u < 4; ++u)
            #pragma unroll
            for (int p = 0; p < 4; ++p)
                acc[u][p] += s_m[sid*17 + u*4 + p];

        #pragma unroll
        for (int u = 0; u < 4; ++u) {
            int co = c0 + grp*4 + u;
            float bc = b[co];
            float lv = 0.f, lq = 0.f;
            #pragma unroll
            for (int p = 0; p < 4; ++p) {
                acc[u][p] += bc; lv += acc[u][p]; lq += acc[u][p]*acc[u][p];
            }
            #pragma unroll
            for (int off = 2; off >= 1; off >>= 1) {
                lv += __shfl_xor_sync(0xffffffffu, lv, off);
                lq += __shfl_xor_sync(0xffffffffu, lq, off);
            }
            float mean = lv * (1.f/16.f);
            float var  = fmaxf(lq * (1.f/16.f) - mean*mean, 0.f);
            float scale = g[co] * rsqrtf(var + EPS);
            float shift = be[co] - mean*scale;
            float4 o;
            o.x = lrelu(acc[u][0]*scale + shift); o.y = lrelu(acc[u][1]*scale + shift);
            o.z = lrelu(acc[u][2]*scale + shift); o.w = lrelu(acc[u][3]*scale + shift);
            *(float4*)(feat + n*4096 + (co << 4) + oy*4) = o;
        }
    }
}

// ============================================================================
// M = feat(256x4096) @ T(4096x3200), register-prefetch (unchanged)
// ============================================================================
__global__ void __launch_bounds__(256) gemmM_kernel(
    const float* __restrict__ A, const float* __restrict__ B)
{
    const int n0 = blockIdx.x * 64;
    const int m0 = blockIdx.y * 64;
    const int tid = threadIdx.x;
    const int tx = tid & 15, ty = tid >> 4;

    __shared__ float sA[16*65];
    __shared__ float sB[16*64];

    float acc[4][4];
    #pragma unroll
    for (int i = 0; i < 4; ++i)
        #pragma unroll
        for (int j = 0; j < 4; ++j) acc[i][j] = 0.f;

    const int lrow = tid >> 2;
    const int lkk  = (tid & 3) << 2;
    const int bk   = tid >> 4;
    const int bj   = (tid & 15) << 2;

    float4 va = *(const float4*)(A + (m0 + lrow)*4096 + lkk);
    float4 vb = *(const float4*)(B + bk*3200 + n0 + bj);

    for (int kt = 0; kt < 4096; kt += 16) {
        sA[(lkk+0)*65 + lrow] = va.x;
        sA[(lkk+1)*65 + lrow] = va.y;
        sA[(lkk+2)*65 + lrow] = va.z;
        sA[(lkk+3)*65 + lrow] = va.w;
        *(float4*)(sB + bk*64 + bj) = vb;
        __syncthreads();
        if (kt + 16 < 4096) {
            va = *(const float4*)(A + (m0 + lrow)*4096 + kt + 16 + lkk);
            vb = *(const float4*)(B + (kt + 16 + bk)*3200 + n0 + bj);
        }
        #pragma unroll
        for (int k = 0; k < 16; ++k) {
            float a[4], bb[4];
            #pragma unroll
            for (int i = 0; i < 4; ++i) a[i]  = sA[k*65 + ty*4 + i];
            #pragma unroll
            for (int j = 0; j < 4; ++j) bb[j] = sB[k*64 + tx*4 + j];
            #pragma unroll
            for (int i = 0; i < 4; ++i)
                #pragma unroll
                for (int j = 0; j < 4; ++j) acc[i][j] += a[i]*bb[j];
        }
        __syncthreads();
    }
    #pragma unroll
    for (int i = 0; i < 4; ++i)
        #pragma unroll
        for (int j = 0; j < 4; ++j)
            g_M[(m0 + ty*4 + i)*3200 + n0 + tx*4 + j] = acc[i][j];
}

// ============================================================================
// o_b: NEW — one block per j; M[j] row staged once; loop o with shfl reduce.
// o_b[j,o] = sum_i exp(-sum_k |M[i,o,k]-M[j,o,k]|) - 1
// ============================================================================
__global__ void __launch_bounds__(256) ob_kernel()
{
    const int j = blockIdx.x;       // 0..255
    const int i = threadIdx.x;      // 0..255 (= row i)

    __shared__ __align__(16) float s_mj[3200];
    __shared__ float s_part[8];

    for (int k = i; k < 3200; k += 256) s_mj[k] = g_M[j*3200 + k];
    __syncthreads();

    const float* mi = g_M + i*3200;
    for (int o = 0; o < 64; ++o) {
        const float2* a2 = (const float2*)(mi + o*50);
        const float2* b2 = (const float2*)(s_mj + o*50);
        float d = 0.f;
        #pragma unroll
        for (int k = 0; k < 25; ++k) {
            float2 a = a2[k], bq = b2[k];
            d += fabsf(a.x - bq.x) + fabsf(a.y - bq.y);
        }
        float e = expf(-d);
        #pragma unroll
        for (int off = 16; off >= 1; off >>= 1)
            e += __shfl_xor_sync(0xffffffffu, e, off);
        if ((i & 31) == 0) s_part[i >> 5] = e;
        __syncthreads();
        if (i == 0) {
            float s = 0.f;
            #pragma unroll
            for (int wq = 0; wq < 8; ++wq) s += s_part[wq];
            g_ob[j*64 + o] = s - 1.0f;
        }
        __syncthreads();
    }
}

// ============================================================================
// y = [feat | o_b] @ fc_w^T + fc_b (unchanged)
// ============================================================================
__global__ void __launch_bounds__(256) fc_kernel(
    const float* __restrict__ feat, const float* __restrict__ Wt,
    const float* __restrict__ bias, float* __restrict__ y)
{
    const int n0 = blockIdx.x * 64;
    const int m0 = blockIdx.y * 64;
    const int tid = threadIdx.x;
    const int tx = tid & 15, ty = tid >> 4;

    __shared__ float sA[16*65];
    __shared__ float sB[16*65];

    float acc[4][4];
    #pragma unroll
    for (int i = 0; i < 4; ++i)
        #pragma unroll
        for (int j = 0; j < 4; ++j) acc[i][j] = 0.f;

    const int lrow = tid >> 2;
    const int lkk  = (tid & 3) << 2;
    const bool bvalid = (n0 + lrow) < 1000;

    float4 va = *(const float4*)(feat + (m0 + lrow)*4096 + lkk);
    float4 vb = bvalid ? *(const float4*)(Wt + (n0 + lrow)*4160 + lkk)
                       : make_float4(0.f, 0.f, 0.f, 0.f);

    for (int kt = 0; kt < 4160; kt += 16) {
        sA[(lkk+0)*65 + lrow] = va.x;
        sA[(lkk+1)*65 + lrow] = va.y;
        sA[(lkk+2)*65 + lrow] = va.z;
        sA[(lkk+3)*65 + lrow] = va.w;
        sB[(lkk+0)*65 + lrow] = vb.x;
        sB[(lkk+1)*65 + lrow] = vb.y;
        sB[(lkk+2)*65 + lrow] = vb.z;
        sB[(lkk+3)*65 + lrow] = vb.w;
        __syncthreads();
        int knext = kt + 16;
        if (knext < 4160) {
            va = (knext < 4096)
               ? *(const float4*)(feat + (m0 + lrow)*4096 + knext + lkk)
               : *(const float4*)(g_ob + (m0 + lrow)*64 + (knext - 4096) + lkk);
            vb = bvalid ? *(const float4*)(Wt + (n0 + lrow)*4160 + knext + lkk)
                        : make_float4(0.f, 0.f, 0.f, 0.f);
        }
        #pragma unroll
        for (int k = 0; k < 16; ++k) {
            float a[4], bb[4];
            #pragma unroll
            for (int i = 0; i < 4; ++i) a[i]  = sA[k*65 + ty*4 + i];
            #pragma unroll
            for (int j = 0; j < 4; ++j) bb[j] = sB[k*65 + tx*4 + j];
            #pragma unroll
            for (int i = 0; i < 4; ++i)
                #pragma unroll
                for (int j = 0; j < 4; ++j) acc[i][j] += a[i]*bb[j];
        }
        __syncthreads();
    }
    #pragma unroll
    for (int i = 0; i < 4; ++i) {
        #pragma unroll
        for (int j = 0; j < 4; ++j) {
            int nn = n0 + tx*4 + j;
            if (nn < 1000)
                y[(m0 + ty*4 + i)*1000 + nn] = acc[i][j] + bias[nn];
        }
    }
}

// ============================================================================
extern "C" void kernel_launch(void* const* d_in, const int* in_sizes, int n_in,
                              void* d_out, int out_size)
{
    (void)in_sizes; (void)n_in; (void)out_size;
    const float* x    = (const float*)d_in[0];
    const float* w1   = (const float*)d_in[1];
    const float* b1   = (const float*)d_in[2];
    const float* g1   = (const float*)d_in[3];
    const float* be1  = (const float*)d_in[4];
    const float* w2   = (const float*)d_in[5];
    const float* b2   = (const float*)d_in[6];
    const float* g2   = (const float*)d_in[7];
    const float* be2  = (const float*)d_in[8];
    const float* w3   = (const float*)d_in[9];
    const float* b3   = (const float*)d_in[10];
    const float* g3   = (const float*)d_in[11];
    const float* be3  = (const float*)d_in[12];
    const float* w4   = (const float*)d_in[13];
    const float* b4   = (const float*)d_in[14];
    const float* g4   = (const float*)d_in[15];
    const float* be4  = (const float*)d_in[16];
    const float* T    = (const float*)d_in[17];
    const float* fc_w = (const float*)d_in[18];
    const float* fc_b = (const float*)d_in[19];

    float* out  = (float*)d_out;
    float* feat = out;                    // (256, 4096)
    float* y    = out + 256*4096;         // (256, 1000)

    conv1_kernel<<<dim3(8, 256), 256>>>(x, w1, b1, g1, be1);
    conv2_kernel<<<dim3(8, 256), 128>>>(w2, b2, g2, be2);
    conv3_kernel<<<dim3(4, 256), 128>>>(w3, b3, g3, be3);
    conv4_kernel<<<dim3(2, 256), 256>>>(w4, b4, g4, be4, feat);
    gemmM_kernel<<<dim3(50, 4), 256>>>(feat, T);
    ob_kernel<<<256, 256>>>();
    fc_kernel<<<dim3(16, 4), 256>>>(feat, fc_w, fc_b, y);
}